// round 10
// baseline (speedup 1.0000x reference)
#include <cuda_runtime.h>

// BinaryMaskEdgeSmoothing, R10: cp.async ring with 2-row (pair) granularity.
//
// Rule (verified rel_err = 0.0 since R4; binary inputs make sum9 and
// gsum = 16*blur exact small ints in f32):
//     out = (gsum >= 9) || (gsum == 8 && cen == 1 && sum9 >= 4)
// via: qual = 6*cen + sum9; adj = qual>9.5 ? 0.6 : 0; out = gsum+adj > 8.5.
//
// R9 was issue-bound (issue 73%, DRAM 73%): per-row barrier/wait/commit/addr
// overhead. R10 amortizes all pipeline overhead over row-pairs: 1 commit
// group = 2 rows, 1 wait + 1 syncthreads per 2 rows, cvta hoisted, 4-pair
// ring (32KB smem), validity checks peeled out of the steady-state loop.

#define IMG_W   1024
#define IMG_H   1024
#define RPB     32            // output rows per block
#define THREADS 256           // 4 cols per thread
#define NPAIRS  17            // input pairs: rows r0-1 .. r0+32
#define ROW_B   (IMG_W * 4)   // bytes per row
#define PAIR_B  (2 * ROW_B)

struct Sums { float t[4], g[4]; };

#define CP_COMMIT() asm volatile("cp.async.commit_group;")
#define CP_WAIT2()  asm volatile("cp.async.wait_group 2;")

__device__ __forceinline__ void cp16(unsigned dst, const float* src) {
    asm volatile("cp.async.cg.shared.global [%0], [%1], 16;" ::
                 "r"(dst), "l"(src));
}

// Issue both rows of pair p (source rows clamped; over-fetch rows are never
// consumed, so clamping is safe).
__device__ __forceinline__ void issue_pair(unsigned sb, const float* gsrc,
                                           int r0, int p) {
    int row0 = r0 - 1 + 2 * p;
    int row1 = min(row0 + 1, IMG_H - 1);
    row0 = min(max(row0, 0), IMG_H - 1);
    unsigned dst = sb + (unsigned)(p & 3) * PAIR_B;
    cp16(dst,         gsrc + (size_t)row0 * IMG_W);
    cp16(dst + ROW_B, gsrc + (size_t)row1 * IMG_W);
}

__device__ __forceinline__ Sums make_sums(const float* __restrict__ row,
                                          int x0, bool hl, bool hr) {
    float4 v = *reinterpret_cast<const float4*>(row + x0);   // LDS.128
    float l = hl ? row[x0 - 1] : 0.f;
    float r = hr ? row[x0 + 4] : 0.f;
    float e0 = l, e1 = v.x, e2 = v.y, e3 = v.z, e4 = v.w, e5 = r;
    Sums s;
    s.t[0] = e0 + e1 + e2;  s.g[0] = s.t[0] + e1;
    s.t[1] = e1 + e2 + e3;  s.g[1] = s.t[1] + e2;
    s.t[2] = e2 + e3 + e4;  s.g[2] = s.t[2] + e3;
    s.t[3] = e3 + e4 + e5;  s.g[3] = s.t[3] + e4;
    return s;
}

__device__ __forceinline__ Sums zero_sums() {
    Sums s;
    #pragma unroll
    for (int j = 0; j < 4; ++j) { s.t[j] = 0.f; s.g[j] = 0.f; }
    return s;
}

__device__ __forceinline__ float4 compute_row(const Sums& A, const Sums& B,
                                              const Sums& C) {
    float res[4];
    #pragma unroll
    for (int j = 0; j < 4; ++j) {
        float sum9 = A.t[j] + B.t[j] + C.t[j];            // 0..9 exact
        float gsum = fmaf(2.f, B.g[j], A.g[j] + C.g[j]);  // 0..16 exact
        float cen  = B.g[j] - B.t[j];                     // 0 or 1
        float qual = fmaf(6.f, cen, sum9);                // >=10 <=> qualify
        float adj  = (qual > 9.5f) ? 0.6f : 0.f;
        res[j] = (gsum + adj > 8.5f) ? 1.f : 0.f;
    }
    return make_float4(res[0], res[1], res[2], res[3]);
}

__global__ void __launch_bounds__(THREADS, 4)
edge_smooth_kernel(const float* __restrict__ in, float* __restrict__ out) {
    __shared__ float buf[4][2][IMG_W];                    // 4-pair ring, 32KB

    const int img = blockIdx.y;
    const int r0  = blockIdx.x * RPB;
    const int tid = threadIdx.x;
    const int x0  = tid * 4;
    const bool hl = (x0 > 0);
    const bool hr = (x0 + 4 < IMG_W);

    const float* gsrc = in + (size_t)img * IMG_H * IMG_W + x0;
    float*       po   = out + ((size_t)img * IMG_H + r0) * IMG_W + x0;

    unsigned sb = (unsigned)__cvta_generic_to_shared(&buf[0][0][0]) + tid * 16u;

    // Prologue: pairs 0,1,2 in flight (3 groups).
    issue_pair(sb, gsrc, r0, 0); CP_COMMIT();
    issue_pair(sb, gsrc, r0, 1); CP_COMMIT();
    issue_pair(sb, gsrc, r0, 2); CP_COMMIT();

    // Prime (pair 0): A = row r0-1 (zeros at image top), B = row r0.
    CP_WAIT2(); __syncthreads();
    issue_pair(sb, gsrc, r0, 3); CP_COMMIT();
    Sums A = (r0 > 0) ? make_sums(buf[0][0], x0, hl, hr) : zero_sums();
    Sums B = make_sums(buf[0][1], x0, hl, hr);

    // Steady state: pairs 1..15 (all rows interior-valid).
    for (int i = 1; i <= 15; ++i) {
        CP_WAIT2(); __syncthreads();
        if (i + 3 < NPAIRS) issue_pair(sb, gsrc, r0, i + 3);
        CP_COMMIT();

        const int s = i & 3;
        Sums C = make_sums(buf[s][0], x0, hl, hr);
        Sums D = make_sums(buf[s][1], x0, hl, hr);

        *reinterpret_cast<float4*>(po)         = compute_row(A, B, C);
        *reinterpret_cast<float4*>(po + IMG_W) = compute_row(B, C, D);
        po += 2 * IMG_W;

        A = C; B = D;
    }

    // Epilogue (pair 16): bottom row r0+32 is zeros at image bottom.
    CP_WAIT2(); __syncthreads();
    {
        Sums C = make_sums(buf[16 & 3][0], x0, hl, hr);
        Sums D = (r0 + RPB < IMG_H) ? make_sums(buf[16 & 3][1], x0, hl, hr)
                                    : zero_sums();
        *reinterpret_cast<float4*>(po)         = compute_row(A, B, C);
        *reinterpret_cast<float4*>(po + IMG_W) = compute_row(B, C, D);
    }
}

extern "C" void kernel_launch(void* const* d_in, const int* in_sizes, int n_in,
                              void* d_out, int out_size) {
    const float* mask = (const float*)d_in[0];   // (B,C,1024,1024) f32
    float*       out  = (float*)d_out;

    int n_imgs = in_sizes[0] / (IMG_H * IMG_W);  // B*C

    dim3 grid(IMG_H / RPB, n_imgs);
    dim3 block(THREADS);
    edge_smooth_kernel<<<grid, block>>>(mask, out);
}

// round 11
// speedup vs baseline: 1.0305x; 1.0305x over previous
#include <cuda_runtime.h>

// BinaryMaskEdgeSmoothing, R11: RPB=16 to fix wave quantization.
//
// R10 analysis: 2048 blocks / 592 resident slots = 3.46 waves -> the final
// partial wave idles ~half the chip for ~1/4 of the runtime (DRAM avg 75%
// despite a healthy steady state). RPB=16 gives 4096 blocks = 6.92 waves
// (~1% tail waste) at the cost of +6.25% read traffic from strip halos.
//
// Rule (verified rel_err = 0.0 since R4; binary inputs make sum9 and
// gsum = 16*blur exact small ints in f32):
//     out = (gsum >= 9) || (gsum == 8 && cen == 1 && sum9 >= 4)
// via: qual = 6*cen + sum9; adj = qual>9.5 ? 0.6 : 0; out = gsum+adj > 8.5.
//
// Pipeline: cp.async pair-granular ring (1 commit group = 2 rows = 8KB),
// 4-pair 32KB smem ring, wait_group(2) + one syncthreads per 2 rows,
// validity checks peeled into prologue/epilogue.

#define IMG_W   1024
#define IMG_H   1024
#define RPB     16            // output rows per block
#define THREADS 256           // 4 cols per thread
#define NPAIRS  ((RPB + 2) / 2)   // 9 input pairs: rows r0-1 .. r0+RPB
#define ROW_B   (IMG_W * 4)   // bytes per row
#define PAIR_B  (2 * ROW_B)

struct Sums { float t[4], g[4]; };

#define CP_COMMIT() asm volatile("cp.async.commit_group;")
#define CP_WAIT2()  asm volatile("cp.async.wait_group 2;")

__device__ __forceinline__ void cp16(unsigned dst, const float* src) {
    asm volatile("cp.async.cg.shared.global [%0], [%1], 16;" ::
                 "r"(dst), "l"(src));
}

// Issue both rows of pair p (source rows clamped; over-fetched rows are never
// consumed, so clamping is safe).
__device__ __forceinline__ void issue_pair(unsigned sb, const float* gsrc,
                                           int r0, int p) {
    int row0 = r0 - 1 + 2 * p;
    int row1 = min(row0 + 1, IMG_H - 1);
    row0 = min(max(row0, 0), IMG_H - 1);
    unsigned dst = sb + (unsigned)(p & 3) * PAIR_B;
    cp16(dst,         gsrc + (size_t)row0 * IMG_W);
    cp16(dst + ROW_B, gsrc + (size_t)row1 * IMG_W);
}

__device__ __forceinline__ Sums make_sums(const float* __restrict__ row,
                                          int x0, bool hl, bool hr) {
    float4 v = *reinterpret_cast<const float4*>(row + x0);   // LDS.128
    float l = hl ? row[x0 - 1] : 0.f;
    float r = hr ? row[x0 + 4] : 0.f;
    float e0 = l, e1 = v.x, e2 = v.y, e3 = v.z, e4 = v.w, e5 = r;
    Sums s;
    s.t[0] = e0 + e1 + e2;  s.g[0] = s.t[0] + e1;
    s.t[1] = e1 + e2 + e3;  s.g[1] = s.t[1] + e2;
    s.t[2] = e2 + e3 + e4;  s.g[2] = s.t[2] + e3;
    s.t[3] = e3 + e4 + e5;  s.g[3] = s.t[3] + e4;
    return s;
}

__device__ __forceinline__ Sums zero_sums() {
    Sums s;
    #pragma unroll
    for (int j = 0; j < 4; ++j) { s.t[j] = 0.f; s.g[j] = 0.f; }
    return s;
}

__device__ __forceinline__ float4 compute_row(const Sums& A, const Sums& B,
                                              const Sums& C) {
    float res[4];
    #pragma unroll
    for (int j = 0; j < 4; ++j) {
        float sum9 = A.t[j] + B.t[j] + C.t[j];            // 0..9 exact
        float gsum = fmaf(2.f, B.g[j], A.g[j] + C.g[j]);  // 0..16 exact
        float cen  = B.g[j] - B.t[j];                     // 0 or 1
        float qual = fmaf(6.f, cen, sum9);                // >=10 <=> qualify
        float adj  = (qual > 9.5f) ? 0.6f : 0.f;
        res[j] = (gsum + adj > 8.5f) ? 1.f : 0.f;
    }
    return make_float4(res[0], res[1], res[2], res[3]);
}

__global__ void __launch_bounds__(THREADS, 4)
edge_smooth_kernel(const float* __restrict__ in, float* __restrict__ out) {
    __shared__ float buf[4][2][IMG_W];                    // 4-pair ring, 32KB

    const int img = blockIdx.y;
    const int r0  = blockIdx.x * RPB;
    const int tid = threadIdx.x;
    const int x0  = tid * 4;
    const bool hl = (x0 > 0);
    const bool hr = (x0 + 4 < IMG_W);

    const float* gsrc = in + (size_t)img * IMG_H * IMG_W + x0;
    float*       po   = out + ((size_t)img * IMG_H + r0) * IMG_W + x0;

    unsigned sb = (unsigned)__cvta_generic_to_shared(&buf[0][0][0]) + tid * 16u;

    // Prologue: pairs 0,1,2 in flight (3 groups).
    issue_pair(sb, gsrc, r0, 0); CP_COMMIT();
    issue_pair(sb, gsrc, r0, 1); CP_COMMIT();
    issue_pair(sb, gsrc, r0, 2); CP_COMMIT();

    // Prime (pair 0): A = row r0-1 (zeros at image top), B = row r0.
    CP_WAIT2(); __syncthreads();
    issue_pair(sb, gsrc, r0, 3); CP_COMMIT();
    Sums A = (r0 > 0) ? make_sums(buf[0][0], x0, hl, hr) : zero_sums();
    Sums B = make_sums(buf[0][1], x0, hl, hr);

    // Steady state: pairs 1..NPAIRS-2 (all rows interior-valid).
    for (int i = 1; i <= NPAIRS - 2; ++i) {
        CP_WAIT2(); __syncthreads();
        if (i + 3 < NPAIRS) issue_pair(sb, gsrc, r0, i + 3);
        CP_COMMIT();

        const int s = i & 3;
        Sums C = make_sums(buf[s][0], x0, hl, hr);
        Sums D = make_sums(buf[s][1], x0, hl, hr);

        *reinterpret_cast<float4*>(po)         = compute_row(A, B, C);
        *reinterpret_cast<float4*>(po + IMG_W) = compute_row(B, C, D);
        po += 2 * IMG_W;

        A = C; B = D;
    }

    // Epilogue (pair NPAIRS-1): bottom row r0+RPB is zeros at image bottom.
    CP_WAIT2(); __syncthreads();
    {
        const int s = (NPAIRS - 1) & 3;
        Sums C = make_sums(buf[s][0], x0, hl, hr);
        Sums D = (r0 + RPB < IMG_H) ? make_sums(buf[s][1], x0, hl, hr)
                                    : zero_sums();
        *reinterpret_cast<float4*>(po)         = compute_row(A, B, C);
        *reinterpret_cast<float4*>(po + IMG_W) = compute_row(B, C, D);
    }
}

extern "C" void kernel_launch(void* const* d_in, const int* in_sizes, int n_in,
                              void* d_out, int out_size) {
    const float* mask = (const float*)d_in[0];   // (B,C,1024,1024) f32
    float*       out  = (float*)d_out;

    int n_imgs = in_sizes[0] / (IMG_H * IMG_W);  // B*C

    dim3 grid(IMG_H / RPB, n_imgs);
    dim3 block(THREADS);
    edge_smooth_kernel<<<grid, block>>>(mask, out);
}